// round 4
// baseline (speedup 1.0000x reference)
#include <cuda_runtime.h>

#define T_STEPS 2048
#define BATCH   256
#define HID     64
#define NG      256
#define NOUT    11

typedef unsigned long long u64;

__device__ float g_hbuf[(size_t)BATCH * T_STEPS * HID];   // 128 MB
__device__ float g_xp[(size_t)BATCH * T_STEPS * NG];      // 512 MB
__device__ float g_hfin[BATCH * HID];

__device__ __forceinline__ u64 pack2(float a, float b) {
    u64 r; asm("mov.b64 %0, {%1,%2};" : "=l"(r) : "f"(a), "f"(b)); return r;
}
__device__ __forceinline__ void unpack2(u64 v, float& a, float& b) {
    asm("mov.b64 {%0,%1}, %2;" : "=f"(a), "=f"(b) : "l"(v));
}
__device__ __forceinline__ void ffma2(u64& d, u64 a, u64 b) {
    asm("fma.rn.f32x2 %0, %1, %2, %0;" : "+l"(d) : "l"(a), "l"(b));
}
__device__ __forceinline__ void fadd2(u64& d, u64 a) {
    asm("add.rn.f32x2 %0, %0, %1;" : "+l"(d) : "l"(a));
}
__device__ __forceinline__ float redu(u64 a0, u64 a1, u64 a2, u64 a3) {
    fadd2(a0, a2); fadd2(a1, a3); fadd2(a0, a1);
    float x, y; unpack2(a0, x, y); return x + y;
}
__device__ __forceinline__ float sigf(float x) {
    return __fdividef(1.0f, 1.0f + __expf(-x));
}
__device__ __forceinline__ float tanh2(float x) { return 2.0f * sigf(2.0f * x) - 1.0f; }

// ---------------------------------------------------------------------------
// Bulk x-projection: g_xp[m][g] = W_ih[g][:] . g_hbuf[m][:] + bias[g]
// Tile = 256 m-rows. Thread -> 2 gate rows (tid&127, +128), 128 m-rows each.
// Each h LDS.128 feeds 4 FFMA2 (both gate rows).
// ---------------------------------------------------------------------------
__global__ __launch_bounds__(256, 1)
void xproj_gemm(const float* __restrict__ W_ih,
                const float* __restrict__ b_ih,
                const float* __restrict__ b_hh)
{
    __shared__ __align__(16) float sh[256 * HID];   // 64 KB
    const int tid = threadIdx.x;
    const size_t m0 = (size_t)blockIdx.x * 256;

    {   // cooperative tile load: 4096 float4, 16 per thread
        const float4* src = (const float4*)(g_hbuf + m0 * HID);
        float4* dst = (float4*)sh;
#pragma unroll
        for (int i = 0; i < 16; i++) dst[tid + i * 256] = src[tid + i * 256];
    }

    const int rowA = tid & 127;
    const int rowB = rowA + 128;
    const int mlo  = (tid >> 7) * 128;

    u64 wA[32], wB[32];
    {
        const float4* pa = (const float4*)(W_ih + rowA * HID);
        const float4* pb = (const float4*)(W_ih + rowB * HID);
#pragma unroll
        for (int i = 0; i < 16; i++) {
            float4 va = pa[i], vb = pb[i];
            wA[2 * i] = pack2(va.x, va.y); wA[2 * i + 1] = pack2(va.z, va.w);
            wB[2 * i] = pack2(vb.x, vb.y); wB[2 * i + 1] = pack2(vb.z, vb.w);
        }
    }
    const float biasA = b_ih[rowA] + b_hh[rowA];
    const float biasB = b_ih[rowB] + b_hh[rowB];
    __syncthreads();

    float* out = g_xp + (m0 + mlo) * NG;
#pragma unroll 2
    for (int m = 0; m < 128; m++) {
        const ulonglong2* hr = (const ulonglong2*)(sh + (mlo + m) * HID);
        u64 aA0 = 0, aA1 = 0, aB0 = 0, aB1 = 0;
#pragma unroll
        for (int k = 0; k < 16; k++) {
            ulonglong2 pv = hr[k];                 // broadcast LDS.128
            ffma2(aA0, pv.x, wA[2 * k]); ffma2(aA1, pv.y, wA[2 * k + 1]);
            ffma2(aB0, pv.x, wB[2 * k]); ffma2(aB1, pv.y, wB[2 * k + 1]);
        }
        fadd2(aA0, aA1); fadd2(aB0, aB1);
        float x, y;
        unpack2(aA0, x, y); out[(size_t)m * NG + rowA] = biasA + x + y;
        unpack2(aB0, x, y); out[(size_t)m * NG + rowB] = biasB + x + y;
    }
}

// ---------------------------------------------------------------------------
// Recurrent kernel. CTA = 2 batch elems, 256 threads. Lane pairs:
//   role0 owns rows (j, 128+j) = (i, g); role1 owns (64+j, 192+j) = (f, o).
// c lives on role1; role0 ships sig(i)*tanh(g) via one shfl.xor(1).
// One barrier per step; sh double-buffered. 4-deep FFMA2 chains, packed reduce.
// ---------------------------------------------------------------------------
template<int MODE>
__global__ __launch_bounds__(256, 1)
void lstm_rec(const float* __restrict__ x_in,
              const float* __restrict__ W_hh,
              const float* __restrict__ W_ih,
              const float* __restrict__ b_ih,
              const float* __restrict__ b_hh)
{
    __shared__ __align__(16) float sh[2][2][HID];
    __shared__ float sx[2][2][2];

    const int tid  = threadIdx.x;
    const int be   = tid >> 7;
    const int r    = tid & 127;
    const int j    = r >> 1;
    const int role = r & 1;
    const int bg   = blockIdx.x * 2 + be;

    const int rowA = role ? (64 + j) : j;
    const int rowB = rowA + 128;

    u64 wA[32], wB[32];
    {
        const float4* pa = (const float4*)(W_hh + rowA * HID);
        const float4* pb = (const float4*)(W_hh + rowB * HID);
#pragma unroll
        for (int i = 0; i < 16; i++) {
            float4 va = pa[i], vb = pb[i];
            wA[2 * i] = pack2(va.x, va.y); wA[2 * i + 1] = pack2(va.z, va.w);
            wB[2 * i] = pack2(vb.x, vb.y); wB[2 * i + 1] = pack2(vb.z, vb.w);
        }
    }

    float biasA = 0.f, biasB = 0.f, wxA0 = 0.f, wxA1 = 0.f, wxB0 = 0.f, wxB1 = 0.f;
    if (MODE == 0) {
        biasA = b_ih[rowA] + b_hh[rowA];
        biasB = b_ih[rowB] + b_hh[rowB];
        wxA0 = W_ih[rowA * 2]; wxA1 = W_ih[rowA * 2 + 1];
        wxB0 = W_ih[rowB * 2]; wxB1 = W_ih[rowB * 2 + 1];
    }

    if (role) sh[0][be][j] = 0.f;

    float xn0 = 0.f, xn1 = 0.f;
    if (MODE == 0 && r == 0) {
        const float2* xq = (const float2*)(x_in + (size_t)bg * T_STEPS * 2);
        float2 x0 = xq[0]; sx[0][be][0] = x0.x; sx[0][be][1] = x0.y;
        float2 x1 = xq[1]; xn0 = x1.x; xn1 = x1.y;
    }

    const float* xpb = g_xp + (size_t)bg * T_STEPS * NG;
    float xpA0 = 0.f, xpB0 = 0.f, xpA1 = 0.f, xpB1 = 0.f;
    if (MODE >= 1) {
        xpA0 = xpb[rowA];      xpB0 = xpb[rowB];
        xpA1 = xpb[NG + rowA]; xpB1 = xpb[NG + rowB];
    }

    float c = 0.f;
    float* hb = g_hbuf + (size_t)bg * T_STEPS * HID + j;
    __syncthreads();

    for (int t = 0; t < T_STEPS; t++) {
        const int p = t & 1;
        const ulonglong2* hr = (const ulonglong2*)sh[p][be];
        // 4 accumulators per row -> chain depth 4
        u64 aA0 = 0, aA1 = 0, aA2 = 0, aA3 = 0;
        u64 aB0 = 0, aB1 = 0, aB2 = 0, aB3 = 0;
#pragma unroll
        for (int k = 0; k < 8; k++) {
            ulonglong2 p0 = hr[2 * k], p1 = hr[2 * k + 1];
            ffma2(aA0, p0.x, wA[4 * k + 0]); ffma2(aA1, p0.y, wA[4 * k + 1]);
            ffma2(aA2, p1.x, wA[4 * k + 2]); ffma2(aA3, p1.y, wA[4 * k + 3]);
            ffma2(aB0, p0.x, wB[4 * k + 0]); ffma2(aB1, p0.y, wB[4 * k + 1]);
            ffma2(aB2, p1.x, wB[4 * k + 2]); ffma2(aB3, p1.y, wB[4 * k + 3]);
        }
        float zA = redu(aA0, aA1, aA2, aA3);
        float zB = redu(aB0, aB1, aB2, aB3);

        if (MODE == 0) {
            float xv0 = sx[p][be][0], xv1 = sx[p][be][1];
            zA += biasA + wxA0 * xv0 + wxA1 * xv1;
            zB += biasB + wxB0 * xv0 + wxB1 * xv1;
        } else {
            zA += xpA0; zB += xpB0;
        }

        // prefetch xp for t+2
        if (MODE >= 1) {
            xpA0 = xpA1; xpB0 = xpB1;
            int tn = (t + 2 < T_STEPS) ? (t + 2) : (T_STEPS - 1);
            xpA1 = xpb[(size_t)tn * NG + rowA];
            xpB1 = xpb[(size_t)tn * NG + rowB];
        }

        // pointwise: uniform up to the shfl
        float sA    = sigf(zA);                        // sig(i) | sig(f)
        float other = role ? sigf(zB) : tanh2(zB);     // sig(o) | tanh(g)
        float send  = sA * other;                      // i*tanh(g) | (unused)
        float ar    = __shfl_xor_sync(0xffffffffu, send, 1);
        if (role) {
            c = sA * c + ar;
            float h = other * tanh2(c);
            sh[p ^ 1][be][j] = h;
            if (MODE <= 1) hb[(size_t)t * HID] = h;
            if (MODE == 2 && t == T_STEPS - 1) g_hfin[bg * HID + j] = h;
        }
        if (MODE == 0 && r == 0) {
            sx[p ^ 1][be][0] = xn0; sx[p ^ 1][be][1] = xn1;
            int tn = (t + 2 < T_STEPS) ? (t + 2) : (T_STEPS - 1);
            const float2* xq = (const float2*)(x_in + (size_t)bg * T_STEPS * 2);
            float2 xv = xq[tn]; xn0 = xv.x; xn1 = xv.y;
        }
        __syncthreads();
    }
}

__global__ void final_linear_kernel(const float* __restrict__ W_out,
                                    const float* __restrict__ b_out,
                                    float* __restrict__ out)
{
    int idx = blockIdx.x * blockDim.x + threadIdx.x;
    if (idx >= BATCH * NOUT) return;
    int b = idx / NOUT, o = idx - b * NOUT;
    float s = b_out[o];
    const float* h  = &g_hfin[b * HID];
    const float* wr = &W_out[o * HID];
#pragma unroll 16
    for (int k = 0; k < HID; k++) s += h[k] * wr[k];
    out[idx] = s;
}

extern "C" void kernel_launch(void* const* d_in, const int* in_sizes, int n_in,
                              void* d_out, int out_size)
{
    const float* x    = (const float*)d_in[0];
    const float* Wih0 = (const float*)d_in[1];
    const float* Whh0 = (const float*)d_in[2];
    const float* bih0 = (const float*)d_in[3];
    const float* bhh0 = (const float*)d_in[4];
    const float* Wih1 = (const float*)d_in[5];
    const float* Whh1 = (const float*)d_in[6];
    const float* bih1 = (const float*)d_in[7];
    const float* bhh1 = (const float*)d_in[8];
    const float* Wih2 = (const float*)d_in[9];
    const float* Whh2 = (const float*)d_in[10];
    const float* bih2 = (const float*)d_in[11];
    const float* bhh2 = (const float*)d_in[12];
    const float* Wout = (const float*)d_in[13];
    const float* bout = (const float*)d_in[14];

    dim3 rgrid(BATCH / 2), rblock(256);
    dim3 ggrid(BATCH * T_STEPS / 256), gblock(256);

    lstm_rec<0><<<rgrid, rblock>>>(x, Whh0, Wih0, bih0, bhh0);
    xproj_gemm<<<ggrid, gblock>>>(Wih1, bih1, bhh1);
    lstm_rec<1><<<rgrid, rblock>>>(nullptr, Whh1, nullptr, nullptr, nullptr);
    xproj_gemm<<<ggrid, gblock>>>(Wih2, bih2, bhh2);
    lstm_rec<2><<<rgrid, rblock>>>(nullptr, Whh2, nullptr, nullptr, nullptr);
    final_linear_kernel<<<(BATCH * NOUT + 255) / 256, 256>>>(Wout, bout, (float*)d_out);
}

// round 5
// speedup vs baseline: 1.0126x; 1.0126x over previous
#include <cuda_runtime.h>

#define T_STEPS 2048
#define BATCH   256
#define HID     64
#define NG      256
#define NOUT    11

typedef unsigned long long u64;

__device__ float g_hbuf[(size_t)BATCH * T_STEPS * HID];   // 128 MB
__device__ float g_xp[(size_t)BATCH * T_STEPS * NG];      // 512 MB
__device__ float g_hfin[BATCH * HID];

__device__ __forceinline__ u64 pack2(float a, float b) {
    u64 r; asm("mov.b64 %0, {%1,%2};" : "=l"(r) : "f"(a), "f"(b)); return r;
}
__device__ __forceinline__ void unpack2(u64 v, float& a, float& b) {
    asm("mov.b64 {%0,%1}, %2;" : "=f"(a), "=f"(b) : "l"(v));
}
__device__ __forceinline__ void ffma2(u64& d, u64 a, u64 b) {
    asm("fma.rn.f32x2 %0, %1, %2, %0;" : "+l"(d) : "l"(a), "l"(b));
}
__device__ __forceinline__ void fadd2(u64& d, u64 a) {
    asm("add.rn.f32x2 %0, %0, %1;" : "+l"(d) : "l"(a));
}
__device__ __forceinline__ float redu(u64 a0, u64 a1, u64 a2, u64 a3) {
    fadd2(a0, a2); fadd2(a1, a3); fadd2(a0, a1);
    float x, y; unpack2(a0, x, y); return x + y;
}
__device__ __forceinline__ float sigf(float x) {
    return __fdividef(1.0f, 1.0f + __expf(-x));
}
__device__ __forceinline__ float tanh2(float x) { return 2.0f * sigf(2.0f * x) - 1.0f; }

// ---------------------------------------------------------------------------
// Bulk x-projection (unchanged from R4 -- measured 451us, near issue floor).
// ---------------------------------------------------------------------------
__global__ __launch_bounds__(256, 1)
void xproj_gemm(const float* __restrict__ W_ih,
                const float* __restrict__ b_ih,
                const float* __restrict__ b_hh)
{
    __shared__ __align__(16) float sh[256 * HID];
    const int tid = threadIdx.x;
    const size_t m0 = (size_t)blockIdx.x * 256;

    {
        const float4* src = (const float4*)(g_hbuf + m0 * HID);
        float4* dst = (float4*)sh;
#pragma unroll
        for (int i = 0; i < 16; i++) dst[tid + i * 256] = src[tid + i * 256];
    }

    const int rowA = tid & 127;
    const int rowB = rowA + 128;
    const int mlo  = (tid >> 7) * 128;

    u64 wA[32], wB[32];
    {
        const float4* pa = (const float4*)(W_ih + rowA * HID);
        const float4* pb = (const float4*)(W_ih + rowB * HID);
#pragma unroll
        for (int i = 0; i < 16; i++) {
            float4 va = pa[i], vb = pb[i];
            wA[2 * i] = pack2(va.x, va.y); wA[2 * i + 1] = pack2(va.z, va.w);
            wB[2 * i] = pack2(vb.x, vb.y); wB[2 * i + 1] = pack2(vb.z, vb.w);
        }
    }
    const float biasA = b_ih[rowA] + b_hh[rowA];
    const float biasB = b_ih[rowB] + b_hh[rowB];
    __syncthreads();

    float* out = g_xp + (m0 + mlo) * NG;
#pragma unroll 2
    for (int m = 0; m < 128; m++) {
        const ulonglong2* hr = (const ulonglong2*)(sh + (mlo + m) * HID);
        u64 aA0 = 0, aA1 = 0, aB0 = 0, aB1 = 0;
#pragma unroll
        for (int k = 0; k < 16; k++) {
            ulonglong2 pv = hr[k];
            ffma2(aA0, pv.x, wA[2 * k]); ffma2(aA1, pv.y, wA[2 * k + 1]);
            ffma2(aB0, pv.x, wB[2 * k]); ffma2(aB1, pv.y, wB[2 * k + 1]);
        }
        fadd2(aA0, aA1); fadd2(aB0, aB1);
        float x, y;
        unpack2(aA0, x, y); out[(size_t)m * NG + rowA] = biasA + x + y;
        unpack2(aB0, x, y); out[(size_t)m * NG + rowB] = biasB + x + y;
    }
}

// ---------------------------------------------------------------------------
// Recurrent kernel, v5: 1 batch elem per CTA, 256 CTAs, 2 CTAs/SM.
// Thread owns ONE gate row: gate = lane&3, unit = wid*8 + (lane>>2),
// row = gate*64 + unit.  Quad lanes (same unit) combine gates via shfl:
//   lane g: act_g = {sig(i), sig(f), tanh(g), sig(o)}[g]
//   xor2: lane0 -> m = sig(i)*tanh(g); lane1 has sig(f)(own) + sig(o)(recv)
//   xor1: lane1 <- m;  lane1: c = sig(f)*c + m; h = sig(o)*tanh(c)
// One __syncthreads per step; h double-buffered in smem.
// ---------------------------------------------------------------------------
template<int MODE>
__global__ __launch_bounds__(256, 2)
void lstm_rec(const float* __restrict__ x_in,
              const float* __restrict__ W_hh,
              const float* __restrict__ W_ih,
              const float* __restrict__ b_ih,
              const float* __restrict__ b_hh)
{
    __shared__ __align__(16) float sh[2][HID];
    __shared__ float sx[2][2];

    const int tid  = threadIdx.x;
    const int lane = tid & 31;
    const int wid  = tid >> 5;
    const int gate = lane & 3;
    const int unit = wid * 8 + (lane >> 2);
    const int row  = gate * 64 + unit;
    const int bg   = blockIdx.x;

    // weight row -> 32 packed f32x2 registers
    u64 w[32];
    {
        const float4* p = (const float4*)(W_hh + row * HID);
#pragma unroll
        for (int i = 0; i < 16; i++) {
            float4 v = p[i];
            w[2 * i] = pack2(v.x, v.y); w[2 * i + 1] = pack2(v.z, v.w);
        }
    }

    float bias = 0.f, wx0 = 0.f, wx1 = 0.f;
    if (MODE == 0) {
        bias = b_ih[row] + b_hh[row];
        wx0 = W_ih[row * 2]; wx1 = W_ih[row * 2 + 1];
    }

    // init h_{-1} = 0 (64 writers: gate-1 lanes)
    if (gate == 1) sh[0][unit] = 0.f;

    // MODE 0: stage x_0, hold x_1 (thread 0)
    float xn0 = 0.f, xn1 = 0.f;
    if (MODE == 0 && tid == 0) {
        const float2* xq = (const float2*)(x_in + (size_t)bg * T_STEPS * 2);
        float2 x0 = xq[0]; sx[0][0] = x0.x; sx[0][1] = x0.y;
        float2 x1 = xq[1]; xn0 = x1.x; xn1 = x1.y;
    }

    // distance-2 xp prefetch
    const float* xpb = g_xp + (size_t)bg * T_STEPS * NG + row;
    float xp0 = 0.f, xp1 = 0.f;
    if (MODE >= 1) { xp0 = xpb[0]; xp1 = xpb[NG]; }

    float c = 0.f;
    float* hb = g_hbuf + (size_t)bg * T_STEPS * HID + unit;
    __syncthreads();

    for (int t = 0; t < T_STEPS; t++) {
        const int p = t & 1;
        const ulonglong2* hr = (const ulonglong2*)sh[p];
        u64 a0 = 0, a1 = 0, a2 = 0, a3 = 0;
#pragma unroll
        for (int k = 0; k < 8; k++) {
            ulonglong2 pv = hr[k * 2], qv = hr[k * 2 + 1];  // broadcast LDS.128
            ffma2(a0, pv.x, w[4 * k + 0]); ffma2(a1, pv.y, w[4 * k + 1]);
            ffma2(a2, qv.x, w[4 * k + 2]); ffma2(a3, qv.y, w[4 * k + 3]);
        }
        float z = redu(a0, a1, a2, a3);

        if (MODE == 0) {
            float xv0 = sx[p][0], xv1 = sx[p][1];
            z += bias + wx0 * xv0 + wx1 * xv1;
        } else {
            z += xp0;
        }

        // prefetch xp for t+2
        if (MODE >= 1) {
            xp0 = xp1;
            int tn = (t + 2 < T_STEPS) ? (t + 2) : (T_STEPS - 1);
            xp1 = xpb[(size_t)tn * NG];
        }

        // quad-lane pointwise
        float act = (gate == 2) ? tanh2(z) : sigf(z);   // i,f,o: sig; g: tanh
        float r2  = __shfl_xor_sync(0xffffffffu, act, 2);
        float m   = act * r2;          // lane0: sig(i)*tanh(g)
        float r1  = __shfl_xor_sync(0xffffffffu, m, 1);
        if (gate == 1) {
            c = act * c + r1;          // sig(f)*c + sig(i)*tanh(g)
            float h = r2 * tanh2(c);   // sig(o)*tanh(c)
            sh[p ^ 1][unit] = h;
            if (MODE <= 1) hb[(size_t)t * HID] = h;
            if (MODE == 2 && t == T_STEPS - 1) g_hfin[bg * HID + unit] = h;
        }
        if (MODE == 0 && tid == 0) {
            sx[p ^ 1][0] = xn0; sx[p ^ 1][1] = xn1;
            int tn = (t + 2 < T_STEPS) ? (t + 2) : (T_STEPS - 1);
            const float2* xq = (const float2*)(x_in + (size_t)bg * T_STEPS * 2);
            float2 xv = xq[tn]; xn0 = xv.x; xn1 = xv.y;
        }
        __syncthreads();
    }
}

__global__ void final_linear_kernel(const float* __restrict__ W_out,
                                    const float* __restrict__ b_out,
                                    float* __restrict__ out)
{
    int idx = blockIdx.x * blockDim.x + threadIdx.x;
    if (idx >= BATCH * NOUT) return;
    int b = idx / NOUT, o = idx - b * NOUT;
    float s = b_out[o];
    const float* h  = &g_hfin[b * HID];
    const float* wr = &W_out[o * HID];
#pragma unroll 16
    for (int k = 0; k < HID; k++) s += h[k] * wr[k];
    out[idx] = s;
}

extern "C" void kernel_launch(void* const* d_in, const int* in_sizes, int n_in,
                              void* d_out, int out_size)
{
    const float* x    = (const float*)d_in[0];
    const float* Wih0 = (const float*)d_in[1];
    const float* Whh0 = (const float*)d_in[2];
    const float* bih0 = (const float*)d_in[3];
    const float* bhh0 = (const float*)d_in[4];
    const float* Wih1 = (const float*)d_in[5];
    const float* Whh1 = (const float*)d_in[6];
    const float* bih1 = (const float*)d_in[7];
    const float* bhh1 = (const float*)d_in[8];
    const float* Wih2 = (const float*)d_in[9];
    const float* Whh2 = (const float*)d_in[10];
    const float* bih2 = (const float*)d_in[11];
    const float* bhh2 = (const float*)d_in[12];
    const float* Wout = (const float*)d_in[13];
    const float* bout = (const float*)d_in[14];

    dim3 rgrid(BATCH), rblock(256);
    dim3 ggrid(BATCH * T_STEPS / 256), gblock(256);

    lstm_rec<0><<<rgrid, rblock>>>(x, Whh0, Wih0, bih0, bhh0);
    xproj_gemm<<<ggrid, gblock>>>(Wih1, bih1, bhh1);
    lstm_rec<1><<<rgrid, rblock>>>(nullptr, Whh1, nullptr, nullptr, nullptr);
    xproj_gemm<<<ggrid, gblock>>>(Wih2, bih2, bhh2);
    lstm_rec<2><<<rgrid, rblock>>>(nullptr, Whh2, nullptr, nullptr, nullptr);
    final_linear_kernel<<<(BATCH * NOUT + 255) / 256, 256>>>(Wout, bout, (float*)d_out);
}

// round 6
// speedup vs baseline: 1.1303x; 1.1162x over previous
#include <cuda_runtime.h>

#define T_STEPS 2048
#define BATCH   256
#define HID     64
#define NG      256
#define NOUT    11

typedef unsigned long long u64;

__device__ float g_hbuf[(size_t)BATCH * T_STEPS * HID];   // 128 MB
__device__ float g_xp[(size_t)BATCH * T_STEPS * NG];      // 512 MB
__device__ float g_hfin[BATCH * HID];

__device__ __forceinline__ u64 pack2(float a, float b) {
    u64 r; asm("mov.b64 %0, {%1,%2};" : "=l"(r) : "f"(a), "f"(b)); return r;
}
__device__ __forceinline__ void unpack2(u64 v, float& a, float& b) {
    asm("mov.b64 {%0,%1}, %2;" : "=f"(a), "=f"(b) : "l"(v));
}
__device__ __forceinline__ void ffma2(u64& d, u64 a, u64 b) {
    asm("fma.rn.f32x2 %0, %1, %2, %0;" : "+l"(d) : "l"(a), "l"(b));
}
__device__ __forceinline__ void fadd2(u64& d, u64 a) {
    asm("add.rn.f32x2 %0, %0, %1;" : "+l"(d) : "l"(a));
}
__device__ __forceinline__ float sigf(float x) {
    return __fdividef(1.0f, 1.0f + __expf(-x));
}
__device__ __forceinline__ float tanh2(float x) { return 2.0f * sigf(2.0f * x) - 1.0f; }

// group barrier: 128 threads, ids 1/2
__device__ __forceinline__ void gbar(int id) {
    asm volatile("bar.sync %0, 128;" :: "r"(id) : "memory");
}

// ---------------------------------------------------------------------------
// Bulk x-projection (R4 version -- measured 450us).
// ---------------------------------------------------------------------------
__global__ __launch_bounds__(256, 1)
void xproj_gemm(const float* __restrict__ W_ih,
                const float* __restrict__ b_ih,
                const float* __restrict__ b_hh)
{
    __shared__ __align__(16) float sh[256 * HID];
    const int tid = threadIdx.x;
    const size_t m0 = (size_t)blockIdx.x * 256;

    {
        const float4* src = (const float4*)(g_hbuf + m0 * HID);
        float4* dst = (float4*)sh;
#pragma unroll
        for (int i = 0; i < 16; i++) dst[tid + i * 256] = src[tid + i * 256];
    }

    const int rowA = tid & 127;
    const int rowB = rowA + 128;
    const int mlo  = (tid >> 7) * 128;

    u64 wA[32], wB[32];
    {
        const float4* pa = (const float4*)(W_ih + rowA * HID);
        const float4* pb = (const float4*)(W_ih + rowB * HID);
#pragma unroll
        for (int i = 0; i < 16; i++) {
            float4 va = pa[i], vb = pb[i];
            wA[2 * i] = pack2(va.x, va.y); wA[2 * i + 1] = pack2(va.z, va.w);
            wB[2 * i] = pack2(vb.x, vb.y); wB[2 * i + 1] = pack2(vb.z, vb.w);
        }
    }
    const float biasA = b_ih[rowA] + b_hh[rowA];
    const float biasB = b_ih[rowB] + b_hh[rowB];
    __syncthreads();

    float* out = g_xp + (m0 + mlo) * NG;
#pragma unroll 2
    for (int m = 0; m < 128; m++) {
        const ulonglong2* hr = (const ulonglong2*)(sh + (mlo + m) * HID);
        u64 aA0 = 0, aA1 = 0, aB0 = 0, aB1 = 0;
#pragma unroll
        for (int k = 0; k < 16; k++) {
            ulonglong2 pv = hr[k];
            ffma2(aA0, pv.x, wA[2 * k]); ffma2(aA1, pv.y, wA[2 * k + 1]);
            ffma2(aB0, pv.x, wB[2 * k]); ffma2(aB1, pv.y, wB[2 * k + 1]);
        }
        fadd2(aA0, aA1); fadd2(aB0, aB1);
        float x, y;
        unpack2(aA0, x, y); out[(size_t)m * NG + rowA] = biasA + x + y;
        unpack2(aB0, x, y); out[(size_t)m * NG + rowB] = biasB + x + y;
    }
}

// ---------------------------------------------------------------------------
// Recurrent kernel: exact R3 structure (best measured), with ONE change:
// per-batch-element named barriers instead of full-CTA __syncthreads.
// Threads 0-127 = elem 0 (bar 1), threads 128-255 = elem 1 (bar 2).
// Warp w sits on SMSP w%4 -> each SMSP holds one warp of each group;
// independent barriers let the two groups' phases interleave.
// ---------------------------------------------------------------------------
template<int MODE>
__global__ __launch_bounds__(256, 1)
void lstm_rec(const float* __restrict__ x_in,
              const float* __restrict__ W_hh,
              const float* __restrict__ W_ih,
              const float* __restrict__ b_ih,
              const float* __restrict__ b_hh)
{
    __shared__ __align__(16) float sh[2][2][HID];  // [buf][be][j]
    __shared__ float sx[2][2][2];

    const int tid  = threadIdx.x;
    const int be   = tid >> 7;
    const int r    = tid & 127;
    const int j    = r >> 1;
    const int role = r & 1;
    const int bg   = blockIdx.x * 2 + be;
    const int bid  = be + 1;                      // named barrier id

    const int rowA = role ? (64 + j) : j;         // (i|f)
    const int rowB = rowA + 128;                  // (g|o)

    u64 wA[32], wB[32];
    {
        const float4* pa = (const float4*)(W_hh + rowA * HID);
        const float4* pb = (const float4*)(W_hh + rowB * HID);
#pragma unroll
        for (int i = 0; i < 16; i++) {
            float4 va = pa[i], vb = pb[i];
            wA[2 * i] = pack2(va.x, va.y); wA[2 * i + 1] = pack2(va.z, va.w);
            wB[2 * i] = pack2(vb.x, vb.y); wB[2 * i + 1] = pack2(vb.z, vb.w);
        }
    }

    float biasA = 0.f, biasB = 0.f, wxA0 = 0.f, wxA1 = 0.f, wxB0 = 0.f, wxB1 = 0.f;
    if (MODE == 0) {
        biasA = b_ih[rowA] + b_hh[rowA];
        biasB = b_ih[rowB] + b_hh[rowB];
        wxA0 = W_ih[rowA * 2]; wxA1 = W_ih[rowA * 2 + 1];
        wxB0 = W_ih[rowB * 2]; wxB1 = W_ih[rowB * 2 + 1];
    }

    if (role) sh[0][be][j] = 0.f;

    float xn0 = 0.f, xn1 = 0.f;
    if (MODE == 0 && r == 0) {
        const float2* xq = (const float2*)(x_in + (size_t)bg * T_STEPS * 2);
        float2 x0 = xq[0]; sx[0][be][0] = x0.x; sx[0][be][1] = x0.y;
        float2 x1 = xq[1]; xn0 = x1.x; xn1 = x1.y;
    }

    const float* xpb = g_xp + (size_t)bg * T_STEPS * NG;
    float xpA0 = 0.f, xpB0 = 0.f, xpA1 = 0.f, xpB1 = 0.f;
    if (MODE >= 1) {
        xpA0 = xpb[rowA];      xpB0 = xpb[rowB];
        xpA1 = xpb[NG + rowA]; xpB1 = xpb[NG + rowB];
    }

    float c = 0.f;
    float* hb = g_hbuf + (size_t)bg * T_STEPS * HID + j;
    __syncthreads();    // one-time: covers init of both groups

    for (int t = 0; t < T_STEPS; t++) {
        const int p = t & 1;
        const ulonglong2* hr = (const ulonglong2*)sh[p][be];
        u64 aA0 = 0, aA1 = 0, aB0 = 0, aB1 = 0;
#pragma unroll
        for (int k = 0; k < 16; k++) {
            ulonglong2 pv = hr[k];                 // broadcast LDS.128
            ffma2(aA0, pv.x, wA[2 * k]); ffma2(aA1, pv.y, wA[2 * k + 1]);
            ffma2(aB0, pv.x, wB[2 * k]); ffma2(aB1, pv.y, wB[2 * k + 1]);
        }
        float zA, zB;
        {
            float u0, u1, u2, u3;
            unpack2(aA0, u0, u1); unpack2(aA1, u2, u3); zA = (u0 + u1) + (u2 + u3);
            unpack2(aB0, u0, u1); unpack2(aB1, u2, u3); zB = (u0 + u1) + (u2 + u3);
        }
        if (MODE == 0) {
            float xv0 = sx[p][be][0], xv1 = sx[p][be][1];
            zA += biasA + wxA0 * xv0 + wxA1 * xv1;
            zB += biasB + wxB0 * xv0 + wxB1 * xv1;
        } else {
            zA += xpA0; zB += xpB0;
        }

        if (MODE >= 1) {
            xpA0 = xpA1; xpB0 = xpB1;
            int tn = (t + 2 < T_STEPS) ? (t + 2) : (T_STEPS - 1);
            xpA1 = xpb[(size_t)tn * NG + rowA];
            xpB1 = xpb[(size_t)tn * NG + rowB];
        }

        float sA    = sigf(zA);                        // sig(i) | sig(f)
        float other = role ? sigf(zB) : tanh2(zB);     // sig(o) | tanh(g)
        float send  = sA * other;                      // i*tanh(g) | --
        float ar    = __shfl_xor_sync(0xffffffffu, send, 1);
        if (role) {
            c = sA * c + ar;
            float h = other * tanh2(c);
            sh[p ^ 1][be][j] = h;
            if (MODE <= 1) hb[(size_t)t * HID] = h;
            if (MODE == 2 && t == T_STEPS - 1) g_hfin[bg * HID + j] = h;
        }
        if (MODE == 0 && r == 0) {
            sx[p ^ 1][be][0] = xn0; sx[p ^ 1][be][1] = xn1;
            int tn = (t + 2 < T_STEPS) ? (t + 2) : (T_STEPS - 1);
            const float2* xq = (const float2*)(x_in + (size_t)bg * T_STEPS * 2);
            float2 xv = xq[tn]; xn0 = xv.x; xn1 = xv.y;
        }
        gbar(bid);      // group-local barrier: the two elems slide independently
    }
}

__global__ void final_linear_kernel(const float* __restrict__ W_out,
                                    const float* __restrict__ b_out,
                                    float* __restrict__ out)
{
    int idx = blockIdx.x * blockDim.x + threadIdx.x;
    if (idx >= BATCH * NOUT) return;
    int b = idx / NOUT, o = idx - b * NOUT;
    float s = b_out[o];
    const float* h  = &g_hfin[b * HID];
    const float* wr = &W_out[o * HID];
#pragma unroll 16
    for (int k = 0; k < HID; k++) s += h[k] * wr[k];
    out[idx] = s;
}

extern "C" void kernel_launch(void* const* d_in, const int* in_sizes, int n_in,
                              void* d_out, int out_size)
{
    const float* x    = (const float*)d_in[0];
    const float* Wih0 = (const float*)d_in[1];
    const float* Whh0 = (const float*)d_in[2];
    const float* bih0 = (const float*)d_in[3];
    const float* bhh0 = (const float*)d_in[4];
    const float* Wih1 = (const float*)d_in[5];
    const float* Whh1 = (const float*)d_in[6];
    const float* bih1 = (const float*)d_in[7];
    const float* bhh1 = (const float*)d_in[8];
    const float* Wih2 = (const float*)d_in[9];
    const float* Whh2 = (const float*)d_in[10];
    const float* bih2 = (const float*)d_in[11];
    const float* bhh2 = (const float*)d_in[12];
    const float* Wout = (const float*)d_in[13];
    const float* bout = (const float*)d_in[14];

    dim3 rgrid(BATCH / 2), rblock(256);
    dim3 ggrid(BATCH * T_STEPS / 256), gblock(256);

    lstm_rec<0><<<rgrid, rblock>>>(x, Whh0, Wih0, bih0, bhh0);
    xproj_gemm<<<ggrid, gblock>>>(Wih1, bih1, bhh1);
    lstm_rec<1><<<rgrid, rblock>>>(nullptr, Whh1, nullptr, nullptr, nullptr);
    xproj_gemm<<<ggrid, gblock>>>(Wih2, bih2, bhh2);
    lstm_rec<2><<<rgrid, rblock>>>(nullptr, Whh2, nullptr, nullptr, nullptr);
    final_linear_kernel<<<(BATCH * NOUT + 255) / 256, 256>>>(Wout, bout, (float*)d_out);
}